// round 12
// baseline (speedup 1.0000x reference)
#include <cuda_runtime.h>

// EmbedDNF: B=128, IN_F=256, HID=512, OUT=128, E=8 (fp32)
//
//   impl[b,i,h,e] = A[i,h,e] + x[b,i,e] * C[i,h,e]
//     A = 1 - cw*cs,  C = cw*(2*cs - 1)       (computed on the fly, fused)
//   h[b,h,e]   = prod_i impl
//   out[b,o,e] = 1 - prod_h (1 - dw[h,o,e] * h[b,h,e])
//
// v3: prep fused into stage1; NB1=32 (halved weight traffic); software-
//     pipelined weight loads; stage3 split across thread pairs + shfl.

#define Bsz   128
#define IN_F  256
#define HID   512
#define OUT_F 128
#define E     8
#define EP    4          // e-pairs

typedef unsigned long long ull;

#define ONE2  0x3F8000003F800000ULL
#define TWO2  0x4000000040000000ULL
#define NEG12 0xBF800000BF800000ULL
#define SGN2  0x8000000080000000ULL

#define ISPL  8                  // i-splits in stage 1
#define IRNG  (IN_F / ISPL)      // 32 i per stage-1 block
#define NB1   32                 // batches per stage-1 block
#define NH1   2                  // h per stage-1 thread (stride 32)

#define NSEG  16                 // h-segments in stage 2
#define HSEG  (HID / NSEG)       // 32
#define NB2   16                 // batches per stage-2 block
#define NO2   2                  // o per stage-2 thread (stride 32)

// -------- scratch (device globals; no allocation) --------
__device__ float g_hpart[ISPL][Bsz][HID][E];             // 16 MB
__device__ float g_pseg[NSEG][Bsz][OUT_F][E];            // 8 MB

// -------- packed f32x2 helpers --------
__device__ __forceinline__ ull fma2(ull a, ull b, ull c) {
    ull d; asm("fma.rn.f32x2 %0, %1, %2, %3;" : "=l"(d) : "l"(a), "l"(b), "l"(c)); return d;
}
__device__ __forceinline__ ull mul2(ull a, ull b) {
    ull d; asm("mul.rn.f32x2 %0, %1, %2;" : "=l"(d) : "l"(a), "l"(b)); return d;
}

// ============================================================
// Kernel 1: stage 1 — h partial products (prep fused)
// grid (HID/64, B/32, ISPL) = (8,4,8) = 256 blocks, 128 threads
// thread = (hl 0..31, epair); NH1=2 h (h0, h0+32); NB1=32 batches
// ============================================================
__global__ __launch_bounds__(128) void stage1_kernel(
    const float* __restrict__ x,
    const float* __restrict__ cw,
    const float* __restrict__ cs)
{
    __shared__ float xs[NB1][IRNG * E];                   // 32 KB

    const int tid   = threadIdx.x;
    const int epair = tid & 3;
    const int hl    = tid >> 2;                           // 0..31
    const int h0    = blockIdx.x * (32 * NH1) + hl;
    const int b0    = blockIdx.y * NB1;
    const int ib    = blockIdx.z * IRNG;

    // stage x[b0..b0+32)[ib..ib+32)[*] : 2048 float4, 16 per thread, coalesced
    for (int t = tid; t < NB1 * IRNG * E / 4; t += 128) {
        int bb = t >> 6;                                  // 64 float4 per batch
        int r  = t & 63;
        const float4* src = reinterpret_cast<const float4*>(
            x + ((size_t)(b0 + bb) * IN_F + ib) * E);
        reinterpret_cast<float4*>(xs[bb])[r] = src[r];
    }
    __syncthreads();

    ull acc[NH1][NB1];
#pragma unroll
    for (int nh = 0; nh < NH1; nh++)
#pragma unroll
        for (int bb = 0; bb < NB1; bb++) acc[nh][bb] = ONE2;

    const ull* cw_u = reinterpret_cast<const ull*>(cw);
    const ull* cs_u = reinterpret_cast<const ull*>(cs);
    const size_t istr = (size_t)HID * EP;
    size_t idx0 = ((size_t)ib * HID + h0) * EP + epair;
    size_t idx1 = idx0 + 32 * EP;

    // software-pipelined weight loads
    ull w0 = cw_u[idx0], s0 = cs_u[idx0];
    ull w1 = cw_u[idx1], s1 = cs_u[idx1];

#pragma unroll 2
    for (int ii = 0; ii < IRNG; ii++) {
        // prefetch next i's weights (clamped on last iter)
        const size_t nstep = (ii < IRNG - 1) ? istr : 0;
        idx0 += nstep; idx1 += nstep;
        ull w0n = cw_u[idx0], s0n = cs_u[idx0];
        ull w1n = cw_u[idx1], s1n = cs_u[idx1];

        // A = 1 - w*s ; C = w*(2s - 1)
        ull A0 = fma2(w0 ^ SGN2, s0, ONE2);
        ull C0 = mul2(w0, fma2(s0, TWO2, NEG12));
        ull A1 = fma2(w1 ^ SGN2, s1, ONE2);
        ull C1 = mul2(w1, fma2(s1, TWO2, NEG12));

#pragma unroll
        for (int bb = 0; bb < NB1; bb++) {
            ull x2 = *reinterpret_cast<const ull*>(&xs[bb][ii * E + epair * 2]);
            acc[0][bb] = mul2(acc[0][bb], fma2(x2, C0, A0));
            acc[1][bb] = mul2(acc[1][bb], fma2(x2, C1, A1));
        }
        w0 = w0n; s0 = s0n; w1 = w1n; s1 = s1n;
    }

#pragma unroll
    for (int nh = 0; nh < NH1; nh++)
#pragma unroll
        for (int bb = 0; bb < NB1; bb++)
            *reinterpret_cast<ull*>(&g_hpart[blockIdx.z][b0 + bb][h0 + nh * 32][epair * 2])
                = acc[nh][bb];
}

// ============================================================
// Kernel 2: stage 2 — out partial products per h-segment
// grid (OUT/64, B/16, NSEG) = (2,8,16) = 256 blocks, 128 threads
// ============================================================
__global__ __launch_bounds__(128) void stage2_kernel(const float* __restrict__ dw) {
    __shared__ float hv[NB2][HSEG * E];                   // 16 KB

    const int tid   = threadIdx.x;
    const int epair = tid & 3;
    const int ob    = tid >> 2;                           // 0..31
    const int o0    = blockIdx.x * (32 * NO2) + ob;
    const int b0    = blockIdx.y * NB2;
    const int hbase = blockIdx.z * HSEG;

    // stage combined h = prod over ISPL partials: 1024 float4, 8 per thread
    for (int t = tid; t < NB2 * HSEG * E / 4; t += 128) {
        int bb = t >> 6;                                  // 64 float4 per batch
        int r  = t & 63;
        const size_t off = (((size_t)(b0 + bb) * HID + hbase) * E) / 4;
        const float4* base = reinterpret_cast<const float4*>(&g_hpart[0][0][0][0]);
        const size_t sstr = (size_t)Bsz * HID * E / 4;
        float4 p = base[off + r];
#pragma unroll
        for (int s = 1; s < ISPL; s++) {
            float4 q = base[s * sstr + off + r];
            p.x *= q.x; p.y *= q.y; p.z *= q.z; p.w *= q.w;
        }
        reinterpret_cast<float4*>(hv[bb])[r] = p;
    }
    __syncthreads();

    ull acc[NO2][NB2];
#pragma unroll
    for (int no = 0; no < NO2; no++)
#pragma unroll
        for (int bb = 0; bb < NB2; bb++) acc[no][bb] = ONE2;

#pragma unroll 2
    for (int hh = 0; hh < HSEG; hh++) {
        const int h = hbase + hh;
        ull ndw0 = *reinterpret_cast<const ull*>(
            dw + ((size_t)h * OUT_F + o0) * E + epair * 2) ^ SGN2;
        ull ndw1 = *reinterpret_cast<const ull*>(
            dw + ((size_t)h * OUT_F + o0 + 32) * E + epair * 2) ^ SGN2;
#pragma unroll
        for (int bb = 0; bb < NB2; bb++) {
            ull hx = *reinterpret_cast<const ull*>(&hv[bb][hh * E + epair * 2]);
            acc[0][bb] = mul2(acc[0][bb], fma2(ndw0, hx, ONE2));     // 1 - dw*h
            acc[1][bb] = mul2(acc[1][bb], fma2(ndw1, hx, ONE2));
        }
    }

#pragma unroll
    for (int no = 0; no < NO2; no++)
#pragma unroll
        for (int bb = 0; bb < NB2; bb++)
            *reinterpret_cast<ull*>(
                &g_pseg[blockIdx.z][b0 + bb][o0 + no * 32][epair * 2]) = acc[no][bb];
}

// ============================================================
// Kernel 3: combine segments: out = 1 - prod_seg P_seg
// thread pairs: each handles 8 segments, combined via shfl_xor.
// 131072 threads, 512 blocks x 256
// ============================================================
__global__ void stage3_kernel(float* __restrict__ out) {
    const int t  = blockIdx.x * blockDim.x + threadIdx.x;     // 0 .. 131071
    const int k  = t >> 1;                                    // ull elem 0..65535
    const int sh = t & 1;                                     // segment half
    const ull* base = reinterpret_cast<const ull*>(&g_pseg[0][0][0][0]);
    const size_t stride = (size_t)Bsz * OUT_F * E / 2;        // 65536 ull per seg
    const int s0 = sh * (NSEG / 2);
    ull p = base[(size_t)s0 * stride + k];
#pragma unroll
    for (int s = 1; s < NSEG / 2; s++)
        p = mul2(p, base[(size_t)(s0 + s) * stride + k]);
    ull q = __shfl_xor_sync(0xFFFFFFFFu, p, 1);
    p = mul2(p, q);
    if (sh == 0) reinterpret_cast<ull*>(out)[k] = fma2(p, NEG12, ONE2);  // 1 - p
}

// ============================================================
extern "C" void kernel_launch(void* const* d_in, const int* in_sizes, int n_in,
                              void* d_out, int out_size) {
    const float* x  = (const float*)d_in[0];   // input        (B, IN_F, E)
    const float* cw = (const float*)d_in[1];   // conj_weights (IN_F, HID, E)
    const float* cs = (const float*)d_in[2];   // conj_signs   (IN_F, HID, E)
    const float* dw = (const float*)d_in[3];   // disj_weights (HID, OUT, E)
    float* out = (float*)d_out;

    stage1_kernel<<<dim3(HID / (32 * NH1), Bsz / NB1, ISPL), 128>>>(x, cw, cs);
    stage2_kernel<<<dim3(OUT_F / (32 * NO2), Bsz / NB2, NSEG), 128>>>(dw);
    stage3_kernel<<<(Bsz * OUT_F * E) / 256, 256>>>(out);

    (void)in_sizes; (void)n_in; (void)out_size;
}